// round 2
// baseline (speedup 1.0000x reference)
#include <cuda_runtime.h>
#include <math.h>

#define INPUT 40
#define HID   512
#define LAT   128
#define BATCH 1024
#define SEQ   512

#define RB   8          // batch rows per block
#define NTH  256        // threads per block
#define NBLK (BATCH/RB) // 128 blocks

// ---------------- device scratch (transposed weights + fused biases) ----------------
__device__ float g_WiT_h [INPUT * 4*HID];
__device__ float g_WhT_h [HID   * 4*HID];
__device__ float g_b_h   [4*HID];
__device__ float g_WiT_mu[HID * 4*LAT];
__device__ float g_WhT_mu[LAT * 4*LAT];
__device__ float g_b_mu  [4*LAT];
__device__ float g_WiT_lv[HID * 4*LAT];
__device__ float g_WhT_lv[LAT * 4*LAT];
__device__ float g_b_lv  [4*LAT];
__device__ float g_WiT_d1[LAT * 4*HID];
__device__ float g_WhT_d1[HID * 4*HID];
__device__ float g_b_d1  [4*HID];
__device__ float g_WiT_d2[HID   * 4*INPUT];
__device__ float g_WhT_d2[INPUT * 4*INPUT];
__device__ float g_b_d2  [4*INPUT];

// ---------------- prep: transpose W[G][K] -> WT[K][G], fuse biases ----------------
__device__ __forceinline__ void transpose_dev(const float* __restrict__ W,
                                              float* __restrict__ WT,
                                              int G, int K, int tid, int nt)
{
    int n = G * K;
    for (int i = tid; i < n; i += nt) {
        int k = i / G;
        int g = i - k * G;
        WT[i] = W[g * K + k];   // WT[k*G+g] = W[g][k]
    }
}

__global__ void prep_kernel(
    const float* Wih_h,  const float* Whh_h,  const float* bih_h,  const float* bhh_h,
    const float* Wih_mu, const float* Whh_mu, const float* bih_mu, const float* bhh_mu,
    const float* Wih_lv, const float* Whh_lv, const float* bih_lv, const float* bhh_lv,
    const float* Wih_d1, const float* Whh_d1, const float* bih_d1, const float* bhh_d1,
    const float* Wih_d2, const float* Whh_d2, const float* bih_d2, const float* bhh_d2)
{
    int tid = blockIdx.x * blockDim.x + threadIdx.x;
    int nt  = gridDim.x * blockDim.x;

    transpose_dev(Wih_h,  g_WiT_h,  4*HID, INPUT, tid, nt);
    transpose_dev(Whh_h,  g_WhT_h,  4*HID, HID,   tid, nt);
    transpose_dev(Wih_mu, g_WiT_mu, 4*LAT, HID,   tid, nt);
    transpose_dev(Whh_mu, g_WhT_mu, 4*LAT, LAT,   tid, nt);
    transpose_dev(Wih_lv, g_WiT_lv, 4*LAT, HID,   tid, nt);
    transpose_dev(Whh_lv, g_WhT_lv, 4*LAT, LAT,   tid, nt);
    transpose_dev(Wih_d1, g_WiT_d1, 4*HID, LAT,   tid, nt);
    transpose_dev(Whh_d1, g_WhT_d1, 4*HID, HID,   tid, nt);
    transpose_dev(Wih_d2, g_WiT_d2, 4*INPUT, HID,   tid, nt);
    transpose_dev(Whh_d2, g_WhT_d2, 4*INPUT, INPUT, tid, nt);

    for (int i = tid; i < 4*HID;   i += nt) g_b_h[i]  = bih_h[i]  + bhh_h[i];
    for (int i = tid; i < 4*LAT;   i += nt) g_b_mu[i] = bih_mu[i] + bhh_mu[i];
    for (int i = tid; i < 4*LAT;   i += nt) g_b_lv[i] = bih_lv[i] + bhh_lv[i];
    for (int i = tid; i < 4*HID;   i += nt) g_b_d1[i] = bih_d1[i] + bhh_d1[i];
    for (int i = tid; i < 4*INPUT; i += nt) g_b_d2[i] = bih_d2[i] + bhh_d2[i];
}

// ---------------- activations (fast, ~1e-6 rel err) ----------------
__device__ __forceinline__ float sigf(float x)
{
    return __fdividef(1.f, 1.f + __expf(-x));
}
__device__ __forceinline__ float tanhf_(float x)
{
    float ax = fabsf(x);
    float t  = __expf(-2.f * ax);
    float r  = __fdividef(1.f - t, 1.f + t);
    return copysignf(r, x);
}

// ---------------- GEMM accumulation: acc[gi][r] += actT[r][k] * WT[k][g0+gi] ----------------
template<int K, int G, int NG>
__device__ __forceinline__ void accum(const float* __restrict__ actT,   // smem [RB][K]
                                      const float* __restrict__ WT,     // gmem [K][G]
                                      int g0, float (&acc)[NG][RB])
{
    #pragma unroll 2
    for (int k = 0; k < K; k++) {
        float a[RB];
        #pragma unroll
        for (int r = 0; r < RB; r++) a[r] = actT[r * K + k];   // broadcast LDS

        const float* wrow = WT + (size_t)k * G + g0;
        float w[NG];
        if constexpr (NG % 4 == 0) {
            #pragma unroll
            for (int v = 0; v < NG / 4; v++) {
                float4 wv = *reinterpret_cast<const float4*>(wrow + 4 * v);
                w[4*v+0] = wv.x; w[4*v+1] = wv.y; w[4*v+2] = wv.z; w[4*v+3] = wv.w;
            }
        } else if constexpr (NG == 2) {
            float2 wv = *reinterpret_cast<const float2*>(wrow);
            w[0] = wv.x; w[1] = wv.y;
        } else {
            #pragma unroll
            for (int v = 0; v < NG; v++) w[v] = wrow[v];
        }

        #pragma unroll
        for (int gi = 0; gi < NG; gi++)
            #pragma unroll
            for (int r = 0; r < RB; r++)
                acc[gi][r] = fmaf(w[gi], a[r], acc[gi][r]);
    }
}

// ---------------- one LSTM cell step for RB batch rows ----------------
// Gate order (PyTorch): i, f, g, o as contiguous chunks of H along the 4H axis.
template<int KIN, int H>
__device__ __forceinline__ void lstm_cell(
    const int t,
    const float* __restrict__ inT,     // smem [RB][KIN]  (input activations)
    float* __restrict__ hT,            // smem [RB][H]    (recurrent h, updated)
    float* __restrict__ cT,            // smem [RB][H]    (cell state, updated)
    const float* __restrict__ WiT,     // gmem [KIN][4H]
    const float* __restrict__ WhT,     // gmem [H][4H]
    const float* __restrict__ bias,    // gmem [4H]
    float* __restrict__ gatesT,        // smem scratch [RB][4H]
    float* __restrict__ outG,          // optional gmem h output (row-major per row)
    size_t row_stride)
{
    constexpr int G  = 4 * H;
    constexpr int NG = (G + NTH - 1) / NTH;
    const int g0 = t * NG;

    if (g0 < G) {
        float acc[NG][RB];
        #pragma unroll
        for (int gi = 0; gi < NG; gi++) {
            float bv = bias[g0 + gi];
            #pragma unroll
            for (int r = 0; r < RB; r++) acc[gi][r] = bv;
        }
        accum<KIN, G, NG>(inT, WiT, g0, acc);
        accum<H,   G, NG>(hT,  WhT, g0, acc);
        #pragma unroll
        for (int r = 0; r < RB; r++)
            #pragma unroll
            for (int gi = 0; gi < NG; gi++)
                gatesT[r * G + g0 + gi] = acc[gi][r];
    }
    __syncthreads();

    for (int idx = t; idx < H * RB; idx += NTH) {
        const int r = idx / H;
        const int j = idx - r * H;
        const float* gr = gatesT + r * G;
        float xi = gr[j];
        float xf = gr[j + H];
        float xg = gr[j + 2 * H];
        float xo = gr[j + 3 * H];
        float c = sigf(xf) * cT[idx] + sigf(xi) * tanhf_(xg);
        float h = sigf(xo) * tanhf_(c);
        cT[idx] = c;
        hT[idx] = h;
        if (outG) outG[row_stride * r + j] = h;
    }
    __syncthreads();
}

// ---------------- main persistent kernel: whole VAE, one launch ----------------
extern __shared__ float smem[];

__global__ void __launch_bounds__(NTH, 1) vae_kernel(
    const float* __restrict__ x,     // [B][S][INPUT]
    const float* __restrict__ eps,   // [B][S][LAT]
    float* __restrict__ out)         // recon [B][S][INPUT] ++ mu [B][S][LAT] ++ logvar [B][S][LAT]
{
    // smem layout (floats), all [row][dim]
    float* gatesT = smem;                        // RB * 4*HID = 16384
    float* hT     = gatesT + RB * 4 * HID;       // RB * HID   =  4096
    float* cT     = hT + RB * HID;               //              4096
    float* hmT    = cT + RB * HID;               // RB * LAT   =  1024
    float* cmT    = hmT + RB * LAT;
    float* hlT    = cmT + RB * LAT;
    float* clT    = hlT + RB * LAT;
    float* h2T    = clT + RB * LAT;              // RB * INPUT =   320
    float* c2T    = h2T + RB * INPUT;
    float* xzT    = c2T + RB * INPUT;            // RB * LAT   =  1024

    const int t  = threadIdx.x;
    const int r0 = blockIdx.x * RB;

    float* reconO = out;
    float* muO    = out + (size_t)BATCH * SEQ * INPUT;
    float* lvO    = muO + (size_t)BATCH * SEQ * LAT;

    // ---- zero encoder state ----
    for (int i = t; i < HID * RB; i += NTH) { hT[i] = 0.f; cT[i] = 0.f; }
    for (int i = t; i < LAT * RB; i += NTH) { hmT[i] = 0.f; cmT[i] = 0.f; hlT[i] = 0.f; clT[i] = 0.f; }
    __syncthreads();

    // ---- encoder ----
    for (int s = 0; s < SEQ; s++) {
        // stage x_t -> xzT [r][k]
        for (int idx = t; idx < INPUT * RB; idx += NTH) {
            int r = idx / INPUT;
            int k = idx - r * INPUT;
            xzT[r * INPUT + k] = x[((size_t)(r0 + r) * SEQ + s) * INPUT + k];
        }
        __syncthreads();

        lstm_cell<INPUT, HID>(t, xzT, hT, cT, g_WiT_h, g_WhT_h, g_b_h, gatesT,
                              (float*)nullptr, 0);
        lstm_cell<HID, LAT>(t, hT, hmT, cmT, g_WiT_mu, g_WhT_mu, g_b_mu, gatesT,
                            muO + ((size_t)r0 * SEQ + s) * LAT, (size_t)SEQ * LAT);
        lstm_cell<HID, LAT>(t, hT, hlT, clT, g_WiT_lv, g_WhT_lv, g_b_lv, gatesT,
                            lvO + ((size_t)r0 * SEQ + s) * LAT, (size_t)SEQ * LAT);
    }

    // ---- zero decoder state ----
    for (int i = t; i < HID * RB; i += NTH) { hT[i] = 0.f; cT[i] = 0.f; }
    for (int i = t; i < INPUT * RB; i += NTH) { h2T[i] = 0.f; c2T[i] = 0.f; }
    __syncthreads();

    // ---- decoder ----
    for (int s = 0; s < SEQ; s++) {
        // stage z_t = mu + eps * exp(0.5*logvar) -> xzT [r][k]
        for (int idx = t; idx < LAT * RB; idx += NTH) {
            int r = idx / LAT;
            int k = idx - r * LAT;
            size_t off = ((size_t)(r0 + r) * SEQ + s) * LAT + k;
            float m = muO[off];
            float l = lvO[off];
            float e = eps[off];
            xzT[r * LAT + k] = fmaf(e, __expf(0.5f * l), m);
        }
        __syncthreads();

        lstm_cell<LAT, HID>(t, xzT, hT, cT, g_WiT_d1, g_WhT_d1, g_b_d1, gatesT,
                            (float*)nullptr, 0);
        lstm_cell<HID, INPUT>(t, hT, h2T, c2T, g_WiT_d2, g_WhT_d2, g_b_d2, gatesT,
                              reconO + ((size_t)r0 * SEQ + s) * INPUT, (size_t)SEQ * INPUT);
    }
}

// ---------------- launcher ----------------
extern "C" void kernel_launch(void* const* d_in, const int* in_sizes, int n_in,
                              void* d_out, int out_size)
{
    (void)in_sizes; (void)n_in; (void)out_size;

    const float* x   = (const float*)d_in[0];
    const float* eps = (const float*)d_in[1];

    prep_kernel<<<512, 256>>>(
        (const float*)d_in[2],  (const float*)d_in[3],  (const float*)d_in[4],  (const float*)d_in[5],
        (const float*)d_in[6],  (const float*)d_in[7],  (const float*)d_in[8],  (const float*)d_in[9],
        (const float*)d_in[10], (const float*)d_in[11], (const float*)d_in[12], (const float*)d_in[13],
        (const float*)d_in[14], (const float*)d_in[15], (const float*)d_in[16], (const float*)d_in[17],
        (const float*)d_in[18], (const float*)d_in[19], (const float*)d_in[20], (const float*)d_in[21]);

    // smem bytes: (16384 + 4096*2 + 1024*4 + 320*2 + 1024) floats = 30336 * 4 = 121344 B
    const int SMEM_BYTES = (RB*4*HID + 2*RB*HID + 4*RB*LAT + 2*RB*INPUT + RB*LAT) * (int)sizeof(float);
    cudaFuncSetAttribute(vae_kernel, cudaFuncAttributeMaxDynamicSharedMemorySize, SMEM_BYTES);

    vae_kernel<<<NBLK, NTH, SMEM_BYTES>>>(x, eps, (float*)d_out);
}

// round 3
// speedup vs baseline: 1.8062x; 1.8062x over previous
#include <cuda_runtime.h>
#include <math.h>

#define INPUT 40
#define HID   512
#define LAT   128
#define BATCH 1024
#define SEQ   512

#define RB   8          // batch rows per block
#define NTH  512        // threads per block
#define NBLK (BATCH/RB) // 128 blocks

typedef unsigned long long u64;

// ---------------- device scratch (transposed weights + fused biases) ----------------
__device__ __align__(16) float g_WiT_h [INPUT * 4*HID];
__device__ __align__(16) float g_WhT_h [HID   * 4*HID];
__device__ __align__(16) float g_b_h   [4*HID];
__device__ __align__(16) float g_WiT_mu[HID * 4*LAT];
__device__ __align__(16) float g_WhT_mu[LAT * 4*LAT];
__device__ __align__(16) float g_b_mu  [4*LAT];
__device__ __align__(16) float g_WiT_lv[HID * 4*LAT];
__device__ __align__(16) float g_WhT_lv[LAT * 4*LAT];
__device__ __align__(16) float g_b_lv  [4*LAT];
__device__ __align__(16) float g_WiT_d1[LAT * 4*HID];
__device__ __align__(16) float g_WhT_d1[HID * 4*HID];
__device__ __align__(16) float g_b_d1  [4*HID];
__device__ __align__(16) float g_WiT_d2[HID   * 4*INPUT];
__device__ __align__(16) float g_WhT_d2[INPUT * 4*INPUT];
__device__ __align__(16) float g_b_d2  [4*INPUT];

// ---------------- prep: transpose W[G][K] -> WT[K][G], fuse biases ----------------
__device__ __forceinline__ void transpose_dev(const float* __restrict__ W,
                                              float* __restrict__ WT,
                                              int G, int K, int tid, int nt)
{
    int n = G * K;
    for (int i = tid; i < n; i += nt) {
        int k = i / G;
        int g = i - k * G;
        WT[i] = W[g * K + k];   // WT[k*G+g] = W[g][k]
    }
}

__global__ void prep_kernel(
    const float* Wih_h,  const float* Whh_h,  const float* bih_h,  const float* bhh_h,
    const float* Wih_mu, const float* Whh_mu, const float* bih_mu, const float* bhh_mu,
    const float* Wih_lv, const float* Whh_lv, const float* bih_lv, const float* bhh_lv,
    const float* Wih_d1, const float* Whh_d1, const float* bih_d1, const float* bhh_d1,
    const float* Wih_d2, const float* Whh_d2, const float* bih_d2, const float* bhh_d2)
{
    int tid = blockIdx.x * blockDim.x + threadIdx.x;
    int nt  = gridDim.x * blockDim.x;

    transpose_dev(Wih_h,  g_WiT_h,  4*HID, INPUT, tid, nt);
    transpose_dev(Whh_h,  g_WhT_h,  4*HID, HID,   tid, nt);
    transpose_dev(Wih_mu, g_WiT_mu, 4*LAT, HID,   tid, nt);
    transpose_dev(Whh_mu, g_WhT_mu, 4*LAT, LAT,   tid, nt);
    transpose_dev(Wih_lv, g_WiT_lv, 4*LAT, HID,   tid, nt);
    transpose_dev(Whh_lv, g_WhT_lv, 4*LAT, LAT,   tid, nt);
    transpose_dev(Wih_d1, g_WiT_d1, 4*HID, LAT,   tid, nt);
    transpose_dev(Whh_d1, g_WhT_d1, 4*HID, HID,   tid, nt);
    transpose_dev(Wih_d2, g_WiT_d2, 4*INPUT, HID,   tid, nt);
    transpose_dev(Whh_d2, g_WhT_d2, 4*INPUT, INPUT, tid, nt);

    for (int i = tid; i < 4*HID;   i += nt) g_b_h[i]  = bih_h[i]  + bhh_h[i];
    for (int i = tid; i < 4*LAT;   i += nt) g_b_mu[i] = bih_mu[i] + bhh_mu[i];
    for (int i = tid; i < 4*LAT;   i += nt) g_b_lv[i] = bih_lv[i] + bhh_lv[i];
    for (int i = tid; i < 4*HID;   i += nt) g_b_d1[i] = bih_d1[i] + bhh_d1[i];
    for (int i = tid; i < 4*INPUT; i += nt) g_b_d2[i] = bih_d2[i] + bhh_d2[i];
}

// ---------------- activations ----------------
__device__ __forceinline__ float sigf(float x)
{
    return __fdividef(1.f, 1.f + __expf(-x));
}
__device__ __forceinline__ float tanhf_(float x)
{
    float ax = fabsf(x);
    float t  = __expf(-2.f * ax);
    float r  = __fdividef(1.f - t, 1.f + t);
    return copysignf(r, x);
}

// ---------------- packed f32x2 fma ----------------
__device__ __forceinline__ void ffma2(u64& d, u64 a, u64 b)
{
    asm("fma.rn.f32x2 %0, %1, %2, %0;" : "+l"(d) : "l"(a), "l"(b));
}
__device__ __forceinline__ u64 pack2(float lo, float hi)
{
    u64 r;
    asm("mov.b64 %0, {%1, %2};" : "=l"(r) : "f"(lo), "f"(hi));
    return r;
}

// ---------------- GEMM accumulation (gate-pair lanes) ----------------
// acc[i][r] (f32x2 lanes = gates g0+2i, g0+2i+1) += aDup[r][k] * WT[k][g0+2i..]
template<int K, int NGP>
__device__ __forceinline__ void accum_pairs(const u64* __restrict__ aDup,  // smem dup [RB][K] (u64 view)
                                            const float* __restrict__ WT,  // gmem [K][G]
                                            int G, int g0, u64 (&acc)[NGP][RB])
{
    #pragma unroll 4
    for (int k = 0; k < K; k++) {
        u64 a[RB];
        #pragma unroll
        for (int r = 0; r < RB; r++) a[r] = aDup[r * K + k];      // LDS.64 broadcast (a,a)

        const u64* w = reinterpret_cast<const u64*>(WT + (size_t)k * G + g0);
        u64 wv[NGP];
        #pragma unroll
        for (int i = 0; i < NGP; i++) wv[i] = w[i];               // packed (w0,w1) from gmem

        #pragma unroll
        for (int i = 0; i < NGP; i++)
            #pragma unroll
            for (int r = 0; r < RB; r++)
                ffma2(acc[i][r], a[r], wv[i]);
    }
}

// runtime K-range variant (for the d2 K-split)
template<int NGP>
__device__ __forceinline__ void accum_pairs_rt(const u64* __restrict__ aDup, int K,
                                               int k0, int k1,
                                               const float* __restrict__ WT,
                                               int G, int g0, u64 (&acc)[NGP][RB])
{
    #pragma unroll 4
    for (int k = k0; k < k1; k++) {
        u64 a[RB];
        #pragma unroll
        for (int r = 0; r < RB; r++) a[r] = aDup[r * K + k];
        const u64* w = reinterpret_cast<const u64*>(WT + (size_t)k * G + g0);
        u64 wv[NGP];
        #pragma unroll
        for (int i = 0; i < NGP; i++) wv[i] = w[i];
        #pragma unroll
        for (int i = 0; i < NGP; i++)
            #pragma unroll
            for (int r = 0; r < RB; r++)
                ffma2(acc[i][r], a[r], wv[i]);
    }
}

// ---------------- elementwise LSTM update ----------------
template<int G, int H>
__device__ __forceinline__ void elem_lstm(const float* __restrict__ gatesT,
                                          float* __restrict__ hDup,
                                          float* __restrict__ cT,
                                          float* __restrict__ outG, size_t rs,
                                          int lt, int nthr)
{
    for (int idx = lt; idx < H * RB; idx += nthr) {
        const int r = idx / H;
        const int j = idx - r * H;
        const float* gr = gatesT + r * G;
        float xi = gr[j];
        float xf = gr[j + H];
        float xg = gr[j + 2 * H];
        float xo = gr[j + 3 * H];
        float c = sigf(xf) * cT[idx] + sigf(xi) * tanhf_(xg);
        float h = sigf(xo) * tanhf_(c);
        cT[idx] = c;
        hDup[2 * idx]     = h;
        hDup[2 * idx + 1] = h;
        if (outG) outG[rs * r + j] = h;
    }
}

// ---------------- main persistent kernel ----------------
extern __shared__ float smem[];

__global__ void __launch_bounds__(NTH, 1) vae_kernel(
    const float* __restrict__ x,     // [B][S][INPUT]
    const float* __restrict__ eps,   // [B][S][LAT]
    float* __restrict__ out)         // recon ++ mu ++ logvar
{
    // smem layout (floats)
    float* gatesT = smem;                         // RB*4*HID = 16384
    float* hDup   = gatesT + RB * 4 * HID;        // RB*HID*2 =  8192
    float* cT     = hDup + RB * HID * 2;          // RB*HID   =  4096
    float* hmDup  = cT + RB * HID;                // RB*LAT*2 =  2048
    float* cmT    = hmDup + RB * LAT * 2;         // RB*LAT   =  1024
    float* hlDup  = cmT + RB * LAT;               //             2048
    float* clT    = hlDup + RB * LAT * 2;         //             1024
    float* h2Dup  = clT + RB * LAT;               // RB*IN*2  =   640
    float* c2T    = h2Dup + RB * INPUT * 2;       // RB*IN    =   320
    float* xzDup  = c2T + RB * INPUT;             // RB*LAT*2 =  2048

    const int t  = threadIdx.x;
    const int r0 = blockIdx.x * RB;

    float* reconO = out;
    float* muO    = out + (size_t)BATCH * SEQ * INPUT;
    float* lvO    = muO + (size_t)BATCH * SEQ * LAT;

    // precomputed small-cell indices
    const int exr = (t < INPUT * RB) ? t / INPUT : 0;       // enc x staging (320 elems)
    const int exk = (t < INPUT * RB) ? t - exr * INPUT : 0;
    const int d2r = (t < INPUT * RB) ? exr : 0;             // d2 elementwise (320 elems)
    const int d2j = (t < INPUT * RB) ? exk : 0;

    // ---- zero encoder state ----
    for (int i = t; i < HID * RB; i += NTH) { hDup[2*i] = 0.f; hDup[2*i+1] = 0.f; cT[i] = 0.f; }
    for (int i = t; i < LAT * RB; i += NTH) {
        hmDup[2*i] = 0.f; hmDup[2*i+1] = 0.f; cmT[i] = 0.f;
        hlDup[2*i] = 0.f; hlDup[2*i+1] = 0.f; clT[i] = 0.f;
    }
    __syncthreads();

    // ================= encoder =================
    for (int s = 0; s < SEQ; s++) {
        // stage x_t (duplicated)
        if (t < INPUT * RB) {
            float v = x[((size_t)(r0 + exr) * SEQ + s) * INPUT + exk];
            xzDup[2 * (exr * INPUT + exk)]     = v;
            xzDup[2 * (exr * INPUT + exk) + 1] = v;
        }
        __syncthreads();

        // ---- h cell: all 512 threads, 4 gates each (2 f32x2 pairs) ----
        {
            constexpr int G = 4 * HID;
            const int g0 = t * 4;
            u64 acc[2][RB];
            #pragma unroll
            for (int i = 0; i < 2; i++) {
                u64 bb = pack2(g_b_h[g0 + 2*i], g_b_h[g0 + 2*i + 1]);
                #pragma unroll
                for (int r = 0; r < RB; r++) acc[i][r] = bb;
            }
            accum_pairs<INPUT, 2>((const u64*)xzDup, g_WiT_h, G, g0, acc);
            accum_pairs<HID,   2>((const u64*)hDup,  g_WhT_h, G, g0, acc);
            #pragma unroll
            for (int r = 0; r < RB; r++)
                #pragma unroll
                for (int i = 0; i < 2; i++)
                    *reinterpret_cast<u64*>(&gatesT[r * G + g0 + 2*i]) = acc[i][r];
        }
        __syncthreads();
        elem_lstm<4*HID, HID>(gatesT, hDup, cT, (float*)nullptr, 0, t, NTH);
        __syncthreads();

        // ---- mu (threads 0..255) & lv (threads 256..511) concurrently ----
        {
            constexpr int G = 4 * LAT;
            float* gMu = gatesT;
            float* gLv = gatesT + RB * G;
            if (t < 256) {
                const int g0 = t * 2;
                u64 acc[1][RB];
                u64 bb = pack2(g_b_mu[g0], g_b_mu[g0 + 1]);
                #pragma unroll
                for (int r = 0; r < RB; r++) acc[0][r] = bb;
                accum_pairs<HID, 1>((const u64*)hDup,  g_WiT_mu, G, g0, acc);
                accum_pairs<LAT, 1>((const u64*)hmDup, g_WhT_mu, G, g0, acc);
                #pragma unroll
                for (int r = 0; r < RB; r++)
                    *reinterpret_cast<u64*>(&gMu[r * G + g0]) = acc[0][r];
            } else {
                const int g0 = (t - 256) * 2;
                u64 acc[1][RB];
                u64 bb = pack2(g_b_lv[g0], g_b_lv[g0 + 1]);
                #pragma unroll
                for (int r = 0; r < RB; r++) acc[0][r] = bb;
                accum_pairs<HID, 1>((const u64*)hDup,  g_WiT_lv, G, g0, acc);
                accum_pairs<LAT, 1>((const u64*)hlDup, g_WhT_lv, G, g0, acc);
                #pragma unroll
                for (int r = 0; r < RB; r++)
                    *reinterpret_cast<u64*>(&gLv[r * G + g0]) = acc[0][r];
            }
        }
        __syncthreads();
        {
            float* gMu = gatesT;
            float* gLv = gatesT + RB * 4 * LAT;
            if (t < 256)
                elem_lstm<4*LAT, LAT>(gMu, hmDup, cmT,
                                      muO + ((size_t)r0 * SEQ + s) * LAT, (size_t)SEQ * LAT,
                                      t, 256);
            else
                elem_lstm<4*LAT, LAT>(gLv, hlDup, clT,
                                      lvO + ((size_t)r0 * SEQ + s) * LAT, (size_t)SEQ * LAT,
                                      t - 256, 256);
        }
        __syncthreads();
    }

    // ---- zero decoder state ----
    for (int i = t; i < HID * RB; i += NTH) { hDup[2*i] = 0.f; hDup[2*i+1] = 0.f; cT[i] = 0.f; }
    for (int i = t; i < INPUT * RB; i += NTH) { h2Dup[2*i] = 0.f; h2Dup[2*i+1] = 0.f; c2T[i] = 0.f; }
    __syncthreads();

    // ================= decoder =================
    for (int s = 0; s < SEQ; s++) {
        // stage z_t = mu + eps * exp(0.5*logvar)  (duplicated)
        for (int idx = t; idx < LAT * RB; idx += NTH) {
            int r = idx >> 7;
            int k = idx & (LAT - 1);
            size_t off = ((size_t)(r0 + r) * SEQ + s) * LAT + k;
            float v = fmaf(eps[off], __expf(0.5f * lvO[off]), muO[off]);
            xzDup[2 * idx]     = v;
            xzDup[2 * idx + 1] = v;
        }
        __syncthreads();

        // ---- d1 cell: all 512 threads ----
        {
            constexpr int G = 4 * HID;
            const int g0 = t * 4;
            u64 acc[2][RB];
            #pragma unroll
            for (int i = 0; i < 2; i++) {
                u64 bb = pack2(g_b_d1[g0 + 2*i], g_b_d1[g0 + 2*i + 1]);
                #pragma unroll
                for (int r = 0; r < RB; r++) acc[i][r] = bb;
            }
            accum_pairs<LAT, 2>((const u64*)xzDup, g_WiT_d1, G, g0, acc);
            accum_pairs<HID, 2>((const u64*)hDup,  g_WhT_d1, G, g0, acc);
            #pragma unroll
            for (int r = 0; r < RB; r++)
                #pragma unroll
                for (int i = 0; i < 2; i++)
                    *reinterpret_cast<u64*>(&gatesT[r * G + g0 + 2*i]) = acc[i][r];
        }
        __syncthreads();
        elem_lstm<4*HID, HID>(gatesT, hDup, cT, (float*)nullptr, 0, t, NTH);
        __syncthreads();

        // ---- d2 cell: K-split across two 80-thread groups ----
        {
            constexpr int G2 = 4 * INPUT;   // 160
            float* gA = gatesT;             // partial A [RB][160]
            float* gB = gatesT + RB * G2;   // partial B [RB][160]
            if (t < 80) {
                const int g0 = t * 2;
                u64 acc[1][RB];
                u64 bb = pack2(g_b_d2[g0], g_b_d2[g0 + 1]);
                #pragma unroll
                for (int r = 0; r < RB; r++) acc[0][r] = bb;
                accum_pairs_rt<1>((const u64*)hDup, HID, 0, 256, g_WiT_d2, G2, g0, acc);
                #pragma unroll
                for (int r = 0; r < RB; r++)
                    *reinterpret_cast<u64*>(&gA[r * G2 + g0]) = acc[0][r];
            } else if (t >= 256 && t < 336) {
                const int g0 = (t - 256) * 2;
                u64 acc[1][RB];
                u64 zz = pack2(0.f, 0.f);
                #pragma unroll
                for (int r = 0; r < RB; r++) acc[0][r] = zz;
                accum_pairs_rt<1>((const u64*)hDup,  HID,   256, HID,   g_WiT_d2, G2, g0, acc);
                accum_pairs_rt<1>((const u64*)h2Dup, INPUT, 0,   INPUT, g_WhT_d2, G2, g0, acc);
                #pragma unroll
                for (int r = 0; r < RB; r++)
                    *reinterpret_cast<u64*>(&gB[r * G2 + g0]) = acc[0][r];
            }
        }
        __syncthreads();
        if (t < INPUT * RB) {
            constexpr int G2 = 4 * INPUT;
            const float* gA = gatesT + d2r * G2;
            const float* gB = gatesT + RB * G2 + d2r * G2;
            const int j = d2j;
            float xi = gA[j]             + gB[j];
            float xf = gA[j + INPUT]     + gB[j + INPUT];
            float xg = gA[j + 2 * INPUT] + gB[j + 2 * INPUT];
            float xo = gA[j + 3 * INPUT] + gB[j + 3 * INPUT];
            const int idx = d2r * INPUT + j;
            float c = sigf(xf) * c2T[idx] + sigf(xi) * tanhf_(xg);
            float h = sigf(xo) * tanhf_(c);
            c2T[idx] = c;
            h2Dup[2 * idx]     = h;
            h2Dup[2 * idx + 1] = h;
            reconO[((size_t)(r0 + d2r) * SEQ + s) * INPUT + j] = h;
        }
        __syncthreads();
    }
}

// ---------------- launcher ----------------
extern "C" void kernel_launch(void* const* d_in, const int* in_sizes, int n_in,
                              void* d_out, int out_size)
{
    (void)in_sizes; (void)n_in; (void)out_size;

    const float* x   = (const float*)d_in[0];
    const float* eps = (const float*)d_in[1];

    prep_kernel<<<512, 256>>>(
        (const float*)d_in[2],  (const float*)d_in[3],  (const float*)d_in[4],  (const float*)d_in[5],
        (const float*)d_in[6],  (const float*)d_in[7],  (const float*)d_in[8],  (const float*)d_in[9],
        (const float*)d_in[10], (const float*)d_in[11], (const float*)d_in[12], (const float*)d_in[13],
        (const float*)d_in[14], (const float*)d_in[15], (const float*)d_in[16], (const float*)d_in[17],
        (const float*)d_in[18], (const float*)d_in[19], (const float*)d_in[20], (const float*)d_in[21]);

    const int SMEM_FLOATS = RB*4*HID          // gatesT
                          + RB*HID*2 + RB*HID // hDup, cT
                          + RB*LAT*2 + RB*LAT // hmDup, cmT
                          + RB*LAT*2 + RB*LAT // hlDup, clT
                          + RB*INPUT*2 + RB*INPUT // h2Dup, c2T
                          + RB*LAT*2;         // xzDup
    const int SMEM_BYTES = SMEM_FLOATS * (int)sizeof(float);
    cudaFuncSetAttribute(vae_kernel, cudaFuncAttributeMaxDynamicSharedMemorySize, SMEM_BYTES);

    vae_kernel<<<NBLK, NTH, SMEM_BYTES>>>(x, eps, (float*)d_out);
}